// round 3
// baseline (speedup 1.0000x reference)
#include <cuda_runtime.h>

// LSTM2LINEAR: B=8192, T=1024, H=10, input scalar.
// One warp per block. 3 batches per warp, 10 lanes per batch (lanes 30,31 are
// dummies mirroring group 2's r=0,1 into a scratch group 3). Hidden state is
// exchanged via a tiny duplicated-pair shared buffer with one __syncwarp per
// step (no block barriers). Gates are computed with packed fma.rn.f32x2:
// (i,f) in one f32x2 accumulator, (g,o) in another. Weights/biases are
// pre-scaled by -log2e (g gate by -2log2e) so the accumulators are directly
// ex2.approx arguments; sigma = rcp(1+e), tanh = 2*rcp(1+e)-1.

#define T_STEPS 1024
#define HDIM 10

typedef unsigned long long ull;

__device__ __forceinline__ ull pk(float lo, float hi) {
    ull v;
    asm("mov.b64 %0, {%1, %2};" : "=l"(v)
        : "r"(__float_as_uint(lo)), "r"(__float_as_uint(hi)));
    return v;
}

__device__ __forceinline__ float2 upk(ull v) {
    unsigned int lo, hi;
    asm("mov.b64 {%0, %1}, %2;" : "=r"(lo), "=r"(hi) : "l"(v));
    return make_float2(__uint_as_float(lo), __uint_as_float(hi));
}

__device__ __forceinline__ ull fma2(ull a, ull b, ull c) {
    ull d;
    asm("fma.rn.f32x2 %0, %1, %2, %3;" : "=l"(d) : "l"(a), "l"(b), "l"(c));
    return d;
}

__device__ __forceinline__ float ex2a(float x) {
    float y; asm("ex2.approx.f32 %0, %1;" : "=f"(y) : "f"(x)); return y;
}

__device__ __forceinline__ float rcpa(float x) {
    float y; asm("rcp.approx.f32 %0, %1;" : "=f"(y) : "f"(x)); return y;
}

__global__ void __launch_bounds__(32)
lstm2linear_kernel(const float* __restrict__ x,      // [B, T]
                   const float* __restrict__ W_ih,   // [4H, 1]
                   const float* __restrict__ W_hh,   // [4H, H]
                   const float* __restrict__ b_ih,   // [4H]
                   const float* __restrict__ b_hh,   // [4H]
                   const float* __restrict__ W_lin,  // [1, H]
                   const float* __restrict__ b_lin,  // [1]
                   float* __restrict__ out,          // [B]
                   int B)
{
    // duplicated-pair h buffers: hs[buf][group][pair j] = {h_j, h_j}
    __shared__ ull hs[2][4][HDIM];

    const int lane = threadIdx.x;
    const int g = lane / HDIM;          // 0..3 (3 = dummy group for lanes 30,31)
    const int r = lane % HDIM;          // 0..9 (lanes 30,31 -> 0,1)
    const int b = blockIdx.x * 3 + g;   // global batch (g==3 is out of use)
    const bool active = (g < 3) && (b < B);
    const int bc = (b < B) ? b : (B - 1);   // clamped batch for safe loads

    const float S1 = -1.4426950408889634f;  // -log2(e)
    const float S2 = -2.8853900817779268f;  // -2*log2(e)

    // ---- per-thread pre-scaled weights (packed across gate pairs) ----
    ull wIF[HDIM], wGO[HDIM];
#pragma unroll
    for (int j = 0; j < HDIM; j++) {
        wIF[j] = pk(S1 * W_hh[(0 * HDIM + r) * HDIM + j],
                    S1 * W_hh[(1 * HDIM + r) * HDIM + j]);
        wGO[j] = pk(S2 * W_hh[(2 * HDIM + r) * HDIM + j],
                    S1 * W_hh[(3 * HDIM + r) * HDIM + j]);
    }
    const ull uIF = pk(S1 * W_ih[0 * HDIM + r], S1 * W_ih[1 * HDIM + r]);
    const ull uGO = pk(S2 * W_ih[2 * HDIM + r], S1 * W_ih[3 * HDIM + r]);
    const ull bIF = pk(S1 * (b_ih[0 * HDIM + r] + b_hh[0 * HDIM + r]),
                       S1 * (b_ih[1 * HDIM + r] + b_hh[1 * HDIM + r]));
    const ull bGO = pk(S2 * (b_ih[2 * HDIM + r] + b_hh[2 * HDIM + r]),
                       S1 * (b_ih[3 * HDIM + r] + b_hh[3 * HDIM + r]));
    const float wlin = W_lin[r];

    float c = 0.0f;

    // zero both buffers (group 3's untouched rows covered by g==0 lanes)
    hs[0][g][r] = 0ull;
    hs[1][g][r] = 0ull;
    if (g == 0) { hs[0][3][r] = 0ull; hs[1][3][r] = 0ull; }
    __syncwarp();

    const float* xb = x + (size_t)bc * T_STEPS;
    int p = 0;

    for (int t0 = 0; t0 < T_STEPS; t0 += 4) {
        const float4 xv = *reinterpret_cast<const float4*>(xb + t0);
#pragma unroll
        for (int k = 0; k < 4; k++) {
            const float xt = (k == 0) ? xv.x : (k == 1) ? xv.y :
                             (k == 2) ? xv.z : xv.w;
            const ull xx = pk(xt, xt);

            // load duplicated h pairs: 5x LDS.128, each half is a {h,h} f32x2 operand
            const ulonglong2* hp =
                reinterpret_cast<const ulonglong2*>(&hs[p][g][0]);
            const ulonglong2 q0 = hp[0], q1 = hp[1], q2 = hp[2],
                             q3 = hp[3], q4 = hp[4];

            ull aIF = fma2(xx, uIF, bIF);
            ull aGO = fma2(xx, uGO, bGO);
            aIF = fma2(wIF[0], q0.x, aIF);  aGO = fma2(wGO[0], q0.x, aGO);
            aIF = fma2(wIF[1], q0.y, aIF);  aGO = fma2(wGO[1], q0.y, aGO);
            aIF = fma2(wIF[2], q1.x, aIF);  aGO = fma2(wGO[2], q1.x, aGO);
            aIF = fma2(wIF[3], q1.y, aIF);  aGO = fma2(wGO[3], q1.y, aGO);
            aIF = fma2(wIF[4], q2.x, aIF);  aGO = fma2(wGO[4], q2.x, aGO);
            aIF = fma2(wIF[5], q2.y, aIF);  aGO = fma2(wGO[5], q2.y, aGO);
            aIF = fma2(wIF[6], q3.x, aIF);  aGO = fma2(wGO[6], q3.x, aGO);
            aIF = fma2(wIF[7], q3.y, aIF);  aGO = fma2(wGO[7], q3.y, aGO);
            aIF = fma2(wIF[8], q4.x, aIF);  aGO = fma2(wGO[8], q4.x, aGO);
            aIF = fma2(wIF[9], q4.y, aIF);  aGO = fma2(wGO[9], q4.y, aGO);

            // accumulators already hold -log2e*gate (g gate: -2log2e*g)
            const float2 gif = upk(aIF);
            const float2 ggo = upk(aGO);
            const float ei = ex2a(gif.x);   // e^{-i}
            const float ef = ex2a(gif.y);   // e^{-f}
            const float eg = ex2a(ggo.x);   // e^{-2g}
            const float eo = ex2a(ggo.y);   // e^{-o}
            const float si = rcpa(1.0f + ei);
            const float sf = rcpa(1.0f + ef);
            const float rg = rcpa(1.0f + eg);
            const float so = rcpa(1.0f + eo);
            const float tg = fmaf(2.0f, rg, -1.0f);

            c = fmaf(sf, c, si * tg);

            const float ec = ex2a(S2 * c);  // e^{-2c}
            const float tc = fmaf(2.0f, rcpa(1.0f + ec), -1.0f);
            const float hn = so * tc;

            hs[p ^ 1][g][r] = pk(hn, hn);
            __syncwarp();
            p ^= 1;
        }
    }

    // ---- output: out[b] = sum_r c_r * W_lin[r] + b_lin ----
    __syncwarp();
    float* scr = reinterpret_cast<float*>(hs);
    scr[g * HDIM + r] = c * wlin;
    __syncwarp();
    if (active && r == 0) {
        float s = b_lin[0];
#pragma unroll
        for (int j = 0; j < HDIM; j++) s += scr[g * HDIM + j];
        out[b] = s;
    }
}

extern "C" void kernel_launch(void* const* d_in, const int* in_sizes, int n_in,
                              void* d_out, int out_size) {
    const float* x     = (const float*)d_in[0];  // [B, T, 1]
    const float* W_ih  = (const float*)d_in[1];  // [4H, 1]
    const float* W_hh  = (const float*)d_in[2];  // [4H, H]
    const float* b_ih  = (const float*)d_in[3];  // [4H]
    const float* b_hh  = (const float*)d_in[4];  // [4H]
    const float* W_lin = (const float*)d_in[5];  // [1, H]
    const float* b_lin = (const float*)d_in[6];  // [1]
    float* out = (float*)d_out;                  // [B, 1]

    const int B = in_sizes[0] / T_STEPS;         // 8192
    const int blocks = (B + 2) / 3;              // 2731 single-warp blocks

    lstm2linear_kernel<<<blocks, 32>>>(x, W_ih, W_hh, b_ih, b_hh,
                                       W_lin, b_lin, out, B);
}

// round 4
// speedup vs baseline: 1.5106x; 1.5106x over previous
#include <cuda_runtime.h>

// LSTM2LINEAR: B=8192, T=1024, H=10, scalar input.
// MUFU-bound kernel: all nonlinearities via tanh.approx.f32 (MUFU.TANH),
// sigma(x) = 0.5*tanh(x/2) + 0.5 with the 0.5 argument scale pre-folded into
// the gate weights/biases -> 5 MUFU per element-step (was 10 with ex2+rcp).
// One warp per block, 3 batches x 10 lanes; h exchanged through a duplicated
// -pair shared buffer ({h,h} per slot) so LDS.128 yields ready f32x2 operands
// for packed fma.rn.f32x2 gate accumulation ((i,f) and (g,o) pairs).
// x is software-pipelined: next float4 loaded before processing current 4 steps.

#define T_STEPS 1024
#define HDIM 10

typedef unsigned long long ull;

__device__ __forceinline__ ull pk(float lo, float hi) {
    ull v;
    asm("mov.b64 %0, {%1, %2};" : "=l"(v)
        : "r"(__float_as_uint(lo)), "r"(__float_as_uint(hi)));
    return v;
}

__device__ __forceinline__ float2 upk(ull v) {
    unsigned int lo, hi;
    asm("mov.b64 {%0, %1}, %2;" : "=r"(lo), "=r"(hi) : "l"(v));
    return make_float2(__uint_as_float(lo), __uint_as_float(hi));
}

__device__ __forceinline__ ull fma2(ull a, ull b, ull c) {
    ull d;
    asm("fma.rn.f32x2 %0, %1, %2, %3;" : "=l"(d) : "l"(a), "l"(b), "l"(c));
    return d;
}

__device__ __forceinline__ float tanha(float x) {
    float y; asm("tanh.approx.f32 %0, %1;" : "=f"(y) : "f"(x)); return y;
}

__global__ void __launch_bounds__(32)
lstm2linear_kernel(const float* __restrict__ x,      // [B, T]
                   const float* __restrict__ W_ih,   // [4H, 1]
                   const float* __restrict__ W_hh,   // [4H, H]
                   const float* __restrict__ b_ih,   // [4H]
                   const float* __restrict__ b_hh,   // [4H]
                   const float* __restrict__ W_lin,  // [1, H]
                   const float* __restrict__ b_lin,  // [1]
                   float* __restrict__ out,          // [B]
                   int B)
{
    // duplicated-pair h buffers: hs[buf][group][j] = {h_j, h_j}
    __shared__ ull hs[2][4][HDIM];

    const int lane = threadIdx.x;
    const int g = lane / HDIM;          // 0..3 (3 = dummy group, lanes 30/31)
    const int r = lane % HDIM;          // 0..9
    const int b = blockIdx.x * 3 + g;
    const bool active = (g < 3) && (b < B);
    const int bc = (b < B) ? b : (B - 1);

    // Pre-fold sigmoid's x/2 into i, f, o gate parameters; g gate unscaled.
    const float HI = 0.5f, HF = 0.5f, HG = 1.0f, HO = 0.5f;

    ull wIF[HDIM], wGO[HDIM];
#pragma unroll
    for (int j = 0; j < HDIM; j++) {
        wIF[j] = pk(HI * W_hh[(0 * HDIM + r) * HDIM + j],
                    HF * W_hh[(1 * HDIM + r) * HDIM + j]);
        wGO[j] = pk(HG * W_hh[(2 * HDIM + r) * HDIM + j],
                    HO * W_hh[(3 * HDIM + r) * HDIM + j]);
    }
    const ull uIF = pk(HI * W_ih[0 * HDIM + r], HF * W_ih[1 * HDIM + r]);
    const ull uGO = pk(HG * W_ih[2 * HDIM + r], HO * W_ih[3 * HDIM + r]);
    const ull bIF = pk(HI * (b_ih[0 * HDIM + r] + b_hh[0 * HDIM + r]),
                       HF * (b_ih[1 * HDIM + r] + b_hh[1 * HDIM + r]));
    const ull bGO = pk(HG * (b_ih[2 * HDIM + r] + b_hh[2 * HDIM + r]),
                       HO * (b_ih[3 * HDIM + r] + b_hh[3 * HDIM + r]));
    const float wlin = W_lin[r];

    float c = 0.0f;

    hs[0][g][r] = 0ull;
    hs[1][g][r] = 0ull;
    if (g == 0) { hs[0][3][r] = 0ull; hs[1][3][r] = 0ull; }
    __syncwarp();

    const float* xb = x + (size_t)bc * T_STEPS;

    // read/write h row pointers, swapped each step
    const ulonglong2* rdp = reinterpret_cast<const ulonglong2*>(&hs[0][g][0]);
    const ulonglong2* wrp = reinterpret_cast<const ulonglong2*>(&hs[1][g][0]);

    // software-pipelined x: load next group before processing current
    float4 xv = *reinterpret_cast<const float4*>(xb);

    for (int t0 = 0; t0 < T_STEPS; t0 += 4) {
        const int tn = (t0 + 4 < T_STEPS) ? (t0 + 4) : t0;
        const float4 xnext = *reinterpret_cast<const float4*>(xb + tn);
#pragma unroll
        for (int k = 0; k < 4; k++) {
            const float xt = (k == 0) ? xv.x : (k == 1) ? xv.y :
                             (k == 2) ? xv.z : xv.w;
            const ull xx = pk(xt, xt);

            const ulonglong2 q0 = rdp[0], q1 = rdp[1], q2 = rdp[2],
                             q3 = rdp[3], q4 = rdp[4];

            ull aIF = fma2(xx, uIF, bIF);
            ull aGO = fma2(xx, uGO, bGO);
            aIF = fma2(wIF[0], q0.x, aIF);  aGO = fma2(wGO[0], q0.x, aGO);
            aIF = fma2(wIF[1], q0.y, aIF);  aGO = fma2(wGO[1], q0.y, aGO);
            aIF = fma2(wIF[2], q1.x, aIF);  aGO = fma2(wGO[2], q1.x, aGO);
            aIF = fma2(wIF[3], q1.y, aIF);  aGO = fma2(wGO[3], q1.y, aGO);
            aIF = fma2(wIF[4], q2.x, aIF);  aGO = fma2(wGO[4], q2.x, aGO);
            aIF = fma2(wIF[5], q2.y, aIF);  aGO = fma2(wGO[5], q2.y, aGO);
            aIF = fma2(wIF[6], q3.x, aIF);  aGO = fma2(wGO[6], q3.x, aGO);
            aIF = fma2(wIF[7], q3.y, aIF);  aGO = fma2(wGO[7], q3.y, aGO);
            aIF = fma2(wIF[8], q4.x, aIF);  aGO = fma2(wGO[8], q4.x, aGO);
            aIF = fma2(wIF[9], q4.y, aIF);  aGO = fma2(wGO[9], q4.y, aGO);

            // aIF = (i/2, f/2), aGO = (g, o/2)
            const float2 gif = upk(aIF);
            const float2 ggo = upk(aGO);
            const float ti = tanha(gif.x);
            const float tf = tanha(gif.y);
            const float tg = tanha(ggo.x);
            const float to = tanha(ggo.y);

            const float si = fmaf(0.5f, ti, 0.5f);   // sigmoid(i)
            const float sf = fmaf(0.5f, tf, 0.5f);   // sigmoid(f)
            c = fmaf(sf, c, si * tg);

            const float tc = tanha(c);
            const float hn = fmaf(0.5f, to, 0.5f) * tc;

            // write to the other buffer, then swap
            const_cast<ull*>(reinterpret_cast<const ull*>(wrp))[r] = pk(hn, hn);
            __syncwarp();
            const ulonglong2* tmp = rdp; rdp = wrp; wrp = tmp;
        }
        xv = xnext;
    }

    // ---- output: out[b] = sum_r c_r * W_lin[r] + b_lin ----
    __syncwarp();
    float* scr = reinterpret_cast<float*>(hs);
    scr[g * HDIM + r] = c * wlin;
    __syncwarp();
    if (active && r == 0) {
        float s = b_lin[0];
#pragma unroll
        for (int j = 0; j < HDIM; j++) s += scr[g * HDIM + j];
        out[b] = s;
    }
}

extern "C" void kernel_launch(void* const* d_in, const int* in_sizes, int n_in,
                              void* d_out, int out_size) {
    const float* x     = (const float*)d_in[0];  // [B, T, 1]
    const float* W_ih  = (const float*)d_in[1];  // [4H, 1]
    const float* W_hh  = (const float*)d_in[2];  // [4H, H]
    const float* b_ih  = (const float*)d_in[3];  // [4H]
    const float* b_hh  = (const float*)d_in[4];  // [4H]
    const float* W_lin = (const float*)d_in[5];  // [1, H]
    const float* b_lin = (const float*)d_in[6];  // [1]
    float* out = (float*)d_out;                  // [B, 1]

    const int B = in_sizes[0] / T_STEPS;         // 8192
    const int blocks = (B + 2) / 3;              // 2731 single-warp blocks

    lstm2linear_kernel<<<blocks, 32>>>(x, W_ih, W_hh, b_ih, b_hh,
                                       W_lin, b_lin, out, B);
}